// round 15
// baseline (speedup 1.0000x reference)
#include <cuda_runtime.h>
#include <stdint.h>

#define NITEMS 100000
#define BROWS  512
#define TOTAL  51200000u        // 512 * 100000
#define QCAP   (1u << 20)
// raw-bits threshold: (bits>>9) >= 8375000  <=>  gumbel >= ~6.44 (conservative;
// row winner clears it w.p. 1-5e-12 per row; pass rate 1.62e-3 -> ~83K survivors)
#define TBITS  (8375000u << 9)
#define FPSCALE 4398046511104.0   // 2^42 fixed-point for deterministic sums

// Device scratch (no allocation allowed)
__device__ float               d_uif[BROWS * 64];
__device__ unsigned long long  d_best[BROWS];
__device__ unsigned int        d_qcount;
__device__ int                 d_is_i32;
__device__ unsigned long long  d_sum_sim;
__device__ unsigned long long  d_sum_loss;
__device__ unsigned int        d_done;
__device__ unsigned long long  d_queue[QCAP];

// rotl(x, R) ^ y with the rotate on the FMA pipe:
// mul.wide.u32 by 2^R gives (x << R) in lo and (x >> (32-R)) in hi;
// (lo | hi) ^ y fuses into one LOP3 on the alu pipe.
template <int R>
__device__ __forceinline__ uint32_t rotxor(uint32_t x, uint32_t y) {
  unsigned long long p;
  asm("mul.wide.u32 %0, %1, %2;" : "=l"(p) : "r"(x), "n"(1u << R));
  return ((uint32_t)p | (uint32_t)(p >> 32)) ^ y;
}

// ---- threefry2x32, key=(0,42), counter (c0=0, c1=i); partitionable 32-bit
// sample = bits1 ^ bits2 (JAX _threefry_random_bits_partitionable, bit_width=32)
__device__ __forceinline__ uint32_t threefry_xor(uint32_t c1) {
  const uint32_t K1 = 42u;
  const uint32_t K2 = 0x1BD11BDAu ^ 42u;
  uint32_t x0 = 0u;            // c0 = 0, + ks[0] = 0
  uint32_t x1 = c1 + K1;       // + ks[1]
#define TFR(r) { x0 += x1; x1 = rotxor<r>(x1, x0); }
#define G1 TFR(13) TFR(15) TFR(26) TFR(6)
#define G2 TFR(17) TFR(29) TFR(16) TFR(24)
  G1  x0 += K1;  x1 += K2 + 1u;
  G2  x0 += K2;  x1 += 2u;
  G1  /* x0 += 0 */ x1 += K1 + 3u;
  G2  x0 += K1;  x1 += K2 + 4u;
  G1  x0 += K2;  x1 += 5u;
#undef G1
#undef G2
#undef TFR
  return x0 ^ x1;
}

// order-preserving float->uint (all values finite)
__device__ __forceinline__ uint32_t orderf(float v) {
  uint32_t u = __float_as_uint(v);
  return (u & 0x80000000u) ? ~u : (u | 0x80000000u);
}
__device__ __forceinline__ unsigned long long packbest(float v, uint32_t n) {
  return (((unsigned long long)orderf(v)) << 32) |
         (unsigned long long)(0xFFFFFFFFu - n);   // ties -> smallest n (like JAX)
}

// ---------------- K1: uif = union_feature @ W.T + b; init; dtype detect --------
__global__ void k_prep(const float* __restrict__ uf, const float* __restrict__ W,
                       const float* __restrict__ bias,
                       const int* __restrict__ need_replace) {
  int b = blockIdx.x;    // 512
  int d = threadIdx.x;   // 64
  __shared__ float su[128];
  su[d]      = uf[b * 128 + d];
  su[d + 64] = uf[b * 128 + 64 + d];
  __syncthreads();
  const float* w = W + d * 128;
  float acc = bias[d];
#pragma unroll 8
  for (int k = 0; k < 128; k++) acc = fmaf(su[k], w[k], acc);
  d_uif[b * 64 + d] = acc;
  if (d == 0) d_best[b] = 0ull;
  if (b == 0) {
    if (d == 0) {
      d_qcount = 0u;
      d_sum_sim = 0ull;
      d_sum_loss = 0ull;
      d_done = 0u;
    }
    // dtype detect: int64 layout -> odd 32-bit words all zero (ids < 2^31);
    // int32 -> odd words are ids; P(32 ids all zero) ~ 1e-160.
    if (d < 32) {
      int v = need_replace[2 * d + 1];
      unsigned any = __ballot_sync(0xFFFFFFFFu, v != 0);
      if (d == 0) d_is_i32 = (any != 0u);
    }
  }
}

// ---------------- K2: threefry sweep + bits-threshold filter -> queue ----------------
__global__ __launch_bounds__(256) void k_sweep() {
  const unsigned t = blockIdx.x * 256u + threadIdx.x;   // 6.4M threads
  const unsigned i0 = t * 8u;                           // 8 consecutive elements
  const int lane = threadIdx.x & 31;
  const unsigned lt = (1u << lane) - 1u;

  uint32_t bits[8];
  bool s[8];
#pragma unroll
  for (int p = 0; p < 8; p++) {
    bits[p] = threefry_xor(i0 + (unsigned)p);
    s[p] = bits[p] >= TBITS;        // i0+p < TOTAL by construction (exact grid)
  }

#pragma unroll
  for (int p = 0; p < 8; p++) {
    unsigned m = __ballot_sync(0xFFFFFFFFu, s[p]);
    if (m) {
      int leader = __ffs(m) - 1;
      unsigned base;
      if (lane == leader) base = atomicAdd(&d_qcount, (unsigned)__popc(m));
      base = __shfl_sync(0xFFFFFFFFu, base, leader);
      if (s[p]) {
        unsigned slot = base + __popc(m & lt);
        if (slot < QCAP)
          d_queue[slot] = (((unsigned long long)bits[p]) << 32) |
                          (unsigned long long)(i0 + (unsigned)p);
      }
    }
  }
}

// ---------------- K3: evaluate survivors (8 threads per survivor, coalesced) ----
__global__ __launch_bounds__(256) void k_eval(const float* __restrict__ A) {
  unsigned cnt = d_qcount;
  if (cnt > QCAP) cnt = QCAP;
  const unsigned ngroups = gridDim.x * 32u;             // 32 groups / block
  const int t8 = threadIdx.x & 7;
  for (unsigned j = blockIdx.x * 32u + (threadIdx.x >> 3); j < cnt; j += ngroups) {
    unsigned long long e = d_queue[j];                  // broadcast load
    uint32_t bits = (uint32_t)(e >> 32);
    uint32_t i    = (uint32_t)e;
    uint32_t row  = i / (unsigned)NITEMS;
    uint32_t n    = i - row * (unsigned)NITEMS;
    const float4* up = (const float4*)(d_uif + row * 64);
    const float4* ap = (const float4*)(A + (size_t)n * 64);
    float4 u0 = up[t8 * 2], u1 = up[t8 * 2 + 1];        // coalesced across group
    float4 a0 = ap[t8 * 2], a1 = ap[t8 * 2 + 1];
    float s = u0.x * a0.x;
    s = fmaf(u0.y, a0.y, s);
    s = fmaf(u0.z, a0.z, s);
    s = fmaf(u0.w, a0.w, s);
    s = fmaf(u1.x, a1.x, s);
    s = fmaf(u1.y, a1.y, s);
    s = fmaf(u1.z, a1.z, s);
    s = fmaf(u1.w, a1.w, s);
    s += __shfl_xor_sync(0xFFFFFFFFu, s, 1);
    s += __shfl_xor_sync(0xFFFFFFFFu, s, 2);
    s += __shfl_xor_sync(0xFFFFFFFFu, s, 4);
    if (t8 == 0) {
      // gumbel exactly as jax (u > 0 guaranteed since bits >= TBITS)
      float u = __uint_as_float((bits >> 9) | 0x3f800000u) - 1.0f;
      float g = -logf(-logf(u));
      atomicMax(&d_best[row], packbest(s + g, n));
    }
  }
}

// ---------------- K4: gather + cosine + deterministic scalar sums ----------------
__global__ __launch_bounds__(64) void k_final(const int* __restrict__ need_replace,
                                              const float* __restrict__ A,
                                              float* __restrict__ out, int out_size) {
  int b = blockIdx.x;    // 512
  int d = threadIdx.x;   // 64
  int wid = d >> 5, lane = d & 31;
  __shared__ float sred[6];

  int jid = d_is_i32 ? need_replace[2 * b + 1]   // int32 layout: nr[b][1]
                     : need_replace[4 * b + 2];  // int64 layout: low word of nr[b][1]

  unsigned long long e = d_best[b];
  uint32_t n = 0xFFFFFFFFu - (uint32_t)(e & 0xFFFFFFFFull);
  if (e == 0ull || n >= (unsigned)NITEMS) n = 0;  // safety (never expected)

  if (d == 0) out[b] = (float)n;  // replaceable_items (exact: n < 2^24)

  float va = A[(size_t)jid * 64 + d];   // items_emb, coalesced
  float vb = A[(size_t)n   * 64 + d];   // replaceable_feat, coalesced
  out[512 + b * 64 + d] = vb;           // coalesced store

  float dot = va * vb, na2 = va * va, nb2 = vb * vb;
#pragma unroll
  for (int o = 16; o; o >>= 1) {
    dot += __shfl_xor_sync(0xFFFFFFFFu, dot, o);
    na2 += __shfl_xor_sync(0xFFFFFFFFu, na2, o);
    nb2 += __shfl_xor_sync(0xFFFFFFFFu, nb2, o);
  }
  if (lane == 0) { sred[wid*3] = dot; sred[wid*3+1] = na2; sred[wid*3+2] = nb2; }
  __syncthreads();
  if (d == 0) {
    float td = sred[0] + sred[3];
    float ta = sred[1] + sred[4];
    float tb = sred[2] + sred[5];
    float denom = fmaxf(sqrtf(ta) * sqrtf(tb), 1e-6f);
    float sim = (td / denom + 1.0f) * 0.5f;
    float lo  = (sim - 0.5f) * (sim - 0.5f);
    // deterministic fixed-point accumulation (integer adds are exact+commutative)
    atomicAdd(&d_sum_sim,  (unsigned long long)(sim * FPSCALE + 0.5));
    atomicAdd(&d_sum_loss, (unsigned long long)(lo  * FPSCALE + 0.5));
    __threadfence();
    unsigned old = atomicAdd(&d_done, 1u);
    if (old == BROWS - 1) {  // last block: all sums visible
      out[out_size - 2] = (float)((double)d_sum_loss / FPSCALE / 512.0);
      out[out_size - 1] = (float)((double)d_sum_sim  / FPSCALE / 512.0);
    }
  }
}

extern "C" void kernel_launch(void* const* d_in, const int* in_sizes, int n_in,
                              void* d_out, int out_size) {
  const int*   need_replace = (const int*)d_in[0];
  const float* uf           = (const float*)d_in[1];
  const float* A            = (const float*)d_in[2];
  const float* W            = (const float*)d_in[3];
  const float* bias         = (const float*)d_in[4];
  float* out = (float*)d_out;

  k_prep<<<512, 64>>>(uf, W, bias, need_replace);
  k_sweep<<<TOTAL / (256u * 8u), 256>>>();   // 25000 blocks, exact coverage
  k_eval<<<2048, 256>>>(A);
  k_final<<<512, 64>>>(need_replace, A, out, out_size);
}

// round 16
// speedup vs baseline: 1.1368x; 1.1368x over previous
#include <cuda_runtime.h>
#include <stdint.h>

#define NITEMS 100000
#define BROWS  512
#define TOTAL  51200000u        // 512 * 100000
#define QCAP   (1u << 20)
// raw-bits threshold: (bits>>9) >= 8375000  <=>  gumbel >= ~6.44 (conservative;
// row winner clears it w.p. 1-5e-12 per row; pass rate 1.62e-3 -> ~83K survivors)
#define TBITS  (8375000u << 9)
#define FPSCALE 4398046511104.0   // 2^42 fixed-point for deterministic sums

// Device scratch (no allocation allowed)
__device__ float               d_uif[BROWS * 64];
__device__ unsigned long long  d_best[BROWS];
__device__ unsigned int        d_qcount;
__device__ int                 d_is_i32;
__device__ unsigned long long  d_sum_sim;
__device__ unsigned long long  d_sum_loss;
__device__ unsigned int        d_done;
__device__ unsigned long long  d_queue[QCAP];

// ---- threefry2x32, key=(0,42), counter (c0=0, c1=i); partitionable 32-bit
// sample = bits1 ^ bits2 (JAX _threefry_random_bits_partitionable, bit_width=32)
__device__ __forceinline__ uint32_t threefry_xor(uint32_t c1) {
  const uint32_t K1 = 42u;
  const uint32_t K2 = 0x1BD11BDAu ^ 42u;
  uint32_t x0 = 0u;            // c0 = 0, + ks[0] = 0
  uint32_t x1 = c1 + K1;       // + ks[1]
#define TFR(r) { x0 += x1; x1 = __funnelshift_l(x1, x1, (r)); x1 ^= x0; }
#define G1 TFR(13) TFR(15) TFR(26) TFR(6)
#define G2 TFR(17) TFR(29) TFR(16) TFR(24)
  G1  x0 += K1;  x1 += K2 + 1u;
  G2  x0 += K2;  x1 += 2u;
  G1  /* x0 += 0 */ x1 += K1 + 3u;
  G2  x0 += K1;  x1 += K2 + 4u;
  G1  x0 += K2;  x1 += 5u;
#undef G1
#undef G2
#undef TFR
  return x0 ^ x1;
}

// order-preserving float->uint (all values finite)
__device__ __forceinline__ uint32_t orderf(float v) {
  uint32_t u = __float_as_uint(v);
  return (u & 0x80000000u) ? ~u : (u | 0x80000000u);
}
__device__ __forceinline__ unsigned long long packbest(float v, uint32_t n) {
  return (((unsigned long long)orderf(v)) << 32) |
         (unsigned long long)(0xFFFFFFFFu - n);   // ties -> smallest n (like JAX)
}

// ---------------- K1: uif = union_feature @ W.T + b; init; dtype detect --------
__global__ void k_prep(const float* __restrict__ uf, const float* __restrict__ W,
                       const float* __restrict__ bias,
                       const int* __restrict__ need_replace) {
  int b = blockIdx.x;    // 512
  int d = threadIdx.x;   // 64
  __shared__ float su[128];
  su[d]      = uf[b * 128 + d];
  su[d + 64] = uf[b * 128 + 64 + d];
  __syncthreads();
  const float* w = W + d * 128;
  float acc = bias[d];
#pragma unroll 8
  for (int k = 0; k < 128; k++) acc = fmaf(su[k], w[k], acc);
  d_uif[b * 64 + d] = acc;
  if (d == 0) d_best[b] = 0ull;
  if (b == 0) {
    if (d == 0) {
      d_qcount = 0u;
      d_sum_sim = 0ull;
      d_sum_loss = 0ull;
      d_done = 0u;
    }
    // dtype detect: int64 layout -> odd 32-bit words all zero (ids < 2^31);
    // int32 -> odd words are ids; P(32 ids all zero) ~ 1e-160.
    if (d < 32) {
      int v = need_replace[2 * d + 1];
      unsigned any = __ballot_sync(0xFFFFFFFFu, v != 0);
      if (d == 0) d_is_i32 = (any != 0u);
    }
  }
}

// ---------------- K2: threefry sweep + bits-threshold filter -> queue ----------------
__global__ __launch_bounds__(256) void k_sweep() {
  const unsigned t = blockIdx.x * 256u + threadIdx.x;   // 6.4M threads
  const unsigned i0 = t * 8u;                           // 8 consecutive elements
  const int lane = threadIdx.x & 31;
  const unsigned lt = (1u << lane) - 1u;

  uint32_t bits[8];
  bool s[8];
#pragma unroll
  for (int p = 0; p < 8; p++) {
    bits[p] = threefry_xor(i0 + (unsigned)p);
    s[p] = bits[p] >= TBITS;        // i0+p < TOTAL by construction (exact grid)
  }

#pragma unroll
  for (int p = 0; p < 8; p++) {
    unsigned m = __ballot_sync(0xFFFFFFFFu, s[p]);
    if (m) {
      int leader = __ffs(m) - 1;
      unsigned base;
      if (lane == leader) base = atomicAdd(&d_qcount, (unsigned)__popc(m));
      base = __shfl_sync(0xFFFFFFFFu, base, leader);
      if (s[p]) {
        unsigned slot = base + __popc(m & lt);
        if (slot < QCAP)
          d_queue[slot] = (((unsigned long long)bits[p]) << 32) |
                          (unsigned long long)(i0 + (unsigned)p);
      }
    }
  }
}

// ---------------- K3: evaluate survivors (8 threads per survivor, coalesced) ----
__global__ __launch_bounds__(256) void k_eval(const float* __restrict__ A) {
  unsigned cnt = d_qcount;
  if (cnt > QCAP) cnt = QCAP;
  const unsigned ngroups = gridDim.x * 32u;             // 32 groups / block
  const int t8 = threadIdx.x & 7;
  for (unsigned j = blockIdx.x * 32u + (threadIdx.x >> 3); j < cnt; j += ngroups) {
    unsigned long long e = d_queue[j];                  // broadcast load
    uint32_t bits = (uint32_t)(e >> 32);
    uint32_t i    = (uint32_t)e;
    uint32_t row  = i / (unsigned)NITEMS;
    uint32_t n    = i - row * (unsigned)NITEMS;
    const float4* up = (const float4*)(d_uif + row * 64);
    const float4* ap = (const float4*)(A + (size_t)n * 64);
    float4 u0 = up[t8 * 2], u1 = up[t8 * 2 + 1];        // coalesced across group
    float4 a0 = ap[t8 * 2], a1 = ap[t8 * 2 + 1];
    float s = u0.x * a0.x;
    s = fmaf(u0.y, a0.y, s);
    s = fmaf(u0.z, a0.z, s);
    s = fmaf(u0.w, a0.w, s);
    s = fmaf(u1.x, a1.x, s);
    s = fmaf(u1.y, a1.y, s);
    s = fmaf(u1.z, a1.z, s);
    s = fmaf(u1.w, a1.w, s);
    s += __shfl_xor_sync(0xFFFFFFFFu, s, 1);
    s += __shfl_xor_sync(0xFFFFFFFFu, s, 2);
    s += __shfl_xor_sync(0xFFFFFFFFu, s, 4);
    if (t8 == 0) {
      // gumbel exactly as jax (u > 0 guaranteed since bits >= TBITS)
      float u = __uint_as_float((bits >> 9) | 0x3f800000u) - 1.0f;
      float g = -logf(-logf(u));
      atomicMax(&d_best[row], packbest(s + g, n));
    }
  }
}

// ---------------- K4: gather + cosine + deterministic scalar sums ----------------
__global__ __launch_bounds__(64) void k_final(const int* __restrict__ need_replace,
                                              const float* __restrict__ A,
                                              float* __restrict__ out, int out_size) {
  int b = blockIdx.x;    // 512
  int d = threadIdx.x;   // 64
  int wid = d >> 5, lane = d & 31;
  __shared__ float sred[6];

  int jid = d_is_i32 ? need_replace[2 * b + 1]   // int32 layout: nr[b][1]
                     : need_replace[4 * b + 2];  // int64 layout: low word of nr[b][1]

  unsigned long long e = d_best[b];
  uint32_t n = 0xFFFFFFFFu - (uint32_t)(e & 0xFFFFFFFFull);
  if (e == 0ull || n >= (unsigned)NITEMS) n = 0;  // safety (never expected)

  if (d == 0) out[b] = (float)n;  // replaceable_items (exact: n < 2^24)

  float va = A[(size_t)jid * 64 + d];   // items_emb, coalesced
  float vb = A[(size_t)n   * 64 + d];   // replaceable_feat, coalesced
  out[512 + b * 64 + d] = vb;           // coalesced store

  float dot = va * vb, na2 = va * va, nb2 = vb * vb;
#pragma unroll
  for (int o = 16; o; o >>= 1) {
    dot += __shfl_xor_sync(0xFFFFFFFFu, dot, o);
    na2 += __shfl_xor_sync(0xFFFFFFFFu, na2, o);
    nb2 += __shfl_xor_sync(0xFFFFFFFFu, nb2, o);
  }
  if (lane == 0) { sred[wid*3] = dot; sred[wid*3+1] = na2; sred[wid*3+2] = nb2; }
  __syncthreads();
  if (d == 0) {
    float td = sred[0] + sred[3];
    float ta = sred[1] + sred[4];
    float tb = sred[2] + sred[5];
    float denom = fmaxf(sqrtf(ta) * sqrtf(tb), 1e-6f);
    float sim = (td / denom + 1.0f) * 0.5f;
    float lo  = (sim - 0.5f) * (sim - 0.5f);
    // deterministic fixed-point accumulation (integer adds are exact+commutative)
    atomicAdd(&d_sum_sim,  (unsigned long long)(sim * FPSCALE + 0.5));
    atomicAdd(&d_sum_loss, (unsigned long long)(lo  * FPSCALE + 0.5));
    __threadfence();
    unsigned old = atomicAdd(&d_done, 1u);
    if (old == BROWS - 1) {  // last block: all sums visible
      out[out_size - 2] = (float)((double)d_sum_loss / FPSCALE / 512.0);
      out[out_size - 1] = (float)((double)d_sum_sim  / FPSCALE / 512.0);
    }
  }
}

extern "C" void kernel_launch(void* const* d_in, const int* in_sizes, int n_in,
                              void* d_out, int out_size) {
  const int*   need_replace = (const int*)d_in[0];
  const float* uf           = (const float*)d_in[1];
  const float* A            = (const float*)d_in[2];
  const float* W            = (const float*)d_in[3];
  const float* bias         = (const float*)d_in[4];
  float* out = (float*)d_out;

  k_prep<<<512, 64>>>(uf, W, bias, need_replace);
  k_sweep<<<TOTAL / (256u * 8u), 256>>>();   // 25000 blocks, exact coverage
  k_eval<<<2048, 256>>>(A);
  k_final<<<512, 64>>>(need_replace, A, out, out_size);
}